// round 1
// baseline (speedup 1.0000x reference)
#include <cuda_runtime.h>

// HOG layer, fused: Sobel conv -> mag/phase -> 9-bin orientation hist -> 8x8 mean pool.
// Input : x  (64,1,512,512) fp32   [d_in[0]]
//         weight (2,1,3,3)  fp32   [d_in[1]] -- fixed Sobel pair, hardcoded below
// Output: (64, 9*64*64) fp32
//
// Block = 256 threads, tile = 32 cols x 16 rows of pixels = 8 cells (4x2).
// Grid  = (512/32, 512/16, 64) = (16, 32, 64).

#define IMG_H 512
#define IMG_W 512
#define ORI   9

// tile + 1-pixel halo on each side
#define T_ROWS 18   // 16 + 2
#define T_COLS 34   // 32 + 2

__global__ __launch_bounds__(256) void hog_kernel(const float* __restrict__ x,
                                                  float* __restrict__ out)
{
    __shared__ float tile[T_ROWS][T_COLS];
    __shared__ float hist[8 * ORI];   // 8 cells x 9 bins

    const int n    = blockIdx.z;
    const int row0 = blockIdx.y * 16;
    const int col0 = blockIdx.x * 32;
    const int tid  = threadIdx.x;

    const float* __restrict__ img = x + (size_t)n * (IMG_H * IMG_W);

    // ---- cooperative halo-tile load with zero padding ----
    for (int i = tid; i < T_ROWS * T_COLS; i += 256) {
        int r  = i / T_COLS;
        int c  = i - r * T_COLS;
        int gr = row0 + r - 1;
        int gc = col0 + c - 1;
        float v = 0.0f;
        if ((unsigned)gr < IMG_H && (unsigned)gc < IMG_W)
            v = img[gr * IMG_W + gc];
        tile[r][c] = v;
    }
    if (tid < 8 * ORI) hist[tid] = 0.0f;
    __syncthreads();

    const int ty = tid >> 5;   // 0..7  (pixel row within half-tile)
    const int tx = tid & 31;   // 0..31 (pixel col)

    // matches float32 rounding of the reference: (phase / pi) * 9
    const float PI_F = 3.14159265358979323846f;  // rounds to 3.14159274f

    #pragma unroll
    for (int p = 0; p < 2; p++) {
        const int py = ty + p * 8;   // 0..15

        // 3x3 neighborhood (cross-correlation, zero pad already in tile)
        float a  = tile[py    ][tx    ];
        float b  = tile[py    ][tx + 1];
        float c  = tile[py    ][tx + 2];
        float d  = tile[py + 1][tx    ];
        float f  = tile[py + 1][tx + 2];
        float g  = tile[py + 2][tx    ];
        float h  = tile[py + 2][tx + 1];
        float i2 = tile[py + 2][tx + 2];

        // w_gx = [[1,0,-1],[2,0,-2],[1,0,-1]], w_gy = transpose
        float gx = (a - c) + 2.0f * (d - f) + (g - i2);
        float gy = (a + 2.0f * b + c) - (g + 2.0f * h + i2);

        float mag   = sqrtf(gx * gx + gy * gy);
        float phase = atan2f(gx, gy);
        float pint  = (phase / PI_F) * 9.0f;   // in [-9, 9]

        float flf = floorf(pint);
        int   fl  = (int)flf;
        int   ce  = (pint == flf) ? fl : fl + 1;   // ceil

        int flm = fl % ORI; if (flm < 0) flm += ORI;
        int cem = ce % ORI; if (cem < 0) cem += ORI;

        const int cell = ((py >> 3) << 2) + (tx >> 3);  // 0..7
        atomicAdd(&hist[cell * ORI + flm], mag);
        atomicAdd(&hist[cell * ORI + cem], mag);
    }
    __syncthreads();

    // ---- write pooled outputs: 8 cells x 9 bins = 72 values ----
    if (tid < 8 * ORI) {
        const int cell = tid / ORI;
        const int o    = tid - cell * ORI;
        const int cy   = cell >> 2;        // 0..1
        const int cx   = cell & 3;         // 0..3
        const int ch   = (row0 >> 3) + cy; // 0..63
        const int cw   = (col0 >> 3) + cx; // 0..63
        // out layout: n * 36864 + o * 4096 + ch * 64 + cw
        out[(size_t)n * (ORI * 64 * 64) + o * (64 * 64) + ch * 64 + cw] =
            hist[tid] * (1.0f / 64.0f);
    }
}

extern "C" void kernel_launch(void* const* d_in, const int* in_sizes, int n_in,
                              void* d_out, int out_size)
{
    const float* x   = (const float*)d_in[0];
    float*       out = (float*)d_out;

    dim3 grid(IMG_W / 32, IMG_H / 16, 64);
    hog_kernel<<<grid, 256>>>(x, out);
}

// round 2
// speedup vs baseline: 1.5661x; 1.5661x over previous
#include <cuda_runtime.h>

// HOG layer, fused: Sobel -> mag/phase -> 9-bin hist -> 8x8 mean pool.
// Input : x (64,1,512,512) fp32. Output: (64, 9*64*64) fp32.
//
// Block = 256 threads = 32 (x) x 8 (y-groups). Tile = 32 cols x 64 rows = 32 cells.
// Each thread column-walks 8 rows (exactly one cell) with register rotation:
// 3 LDS per pixel. Per-thread private smem histogram -> no atomics.

#define IMG_H 512
#define IMG_W 512
#define ORI   9

#define TILE_W 32
#define TILE_H 64
#define T_COLS 34   // 32 + 2 halo
#define T_ROWS 66   // 64 + 2 halo

__global__ __launch_bounds__(256) void hog_kernel(const float* __restrict__ x,
                                                  float* __restrict__ out)
{
    __shared__ float tile[T_ROWS][T_COLS];
    __shared__ float hist[10][256];   // [slot][tid]; slot 9 folds into slot 0

    const int n    = blockIdx.z;
    const int row0 = blockIdx.y * TILE_H;
    const int col0 = blockIdx.x * TILE_W;
    const int tid  = threadIdx.x;
    const int tx   = tid & 31;   // column within tile (also lane)
    const int ty   = tid >> 5;   // cell-row group 0..7 (also warp id)

    const float* __restrict__ img = x + (size_t)n * (IMG_H * IMG_W);

    // ---- cooperative halo-tile load (zero padding) ----
    for (int i = tid; i < T_ROWS * T_COLS; i += 256) {
        int r  = i / T_COLS;
        int c  = i - r * T_COLS;
        int gr = row0 + r - 1;
        int gc = col0 + c - 1;
        float v = 0.0f;
        if ((unsigned)gr < IMG_H && (unsigned)gc < IMG_W)
            v = img[gr * IMG_W + gc];
        tile[r][c] = v;
    }
    #pragma unroll
    for (int b = 0; b < 10; b++) hist[b][tid] = 0.0f;
    __syncthreads();

    // float32 pi, matching reference rounding of (phase / pi) * 9
    const float PI_F = 3.14159265358979323846f;

    // ---- column walk: rows ty*8 .. ty*8+7 at column tx ----
    const int rbase = ty * 8;   // tile-row of (output row - 1) for step 0

    float t0, t1, t2;   // left - right        per row
    float h0, h1, h2;   // left + 2*mid + right per row
    {
        float l = tile[rbase][tx];
        float m = tile[rbase][tx + 1];
        float r = tile[rbase][tx + 2];
        t0 = l - r;  h0 = l + 2.0f * m + r;
        l = tile[rbase + 1][tx];
        m = tile[rbase + 1][tx + 1];
        r = tile[rbase + 1][tx + 2];
        t1 = l - r;  h1 = l + 2.0f * m + r;
    }

    #pragma unroll
    for (int s = 0; s < 8; s++) {
        float l = tile[rbase + s + 2][tx];
        float m = tile[rbase + s + 2][tx + 1];
        float r = tile[rbase + s + 2][tx + 2];
        t2 = l - r;  h2 = l + 2.0f * m + r;

        float gx = t0 + 2.0f * t1 + t2;
        float gy = h0 - h2;

        float mag   = sqrtf(gx * gx + gy * gy);
        float phase = atan2f(gx, gy);
        float pint  = (phase / PI_F) * 9.0f;   // [-9, 9]

        float flf = floorf(pint);
        int   fl  = (int)flf;                  // [-9, 9]
        int   flm = fl + ((fl < 0) ? 9 : 0);   // mod 9 into [0, 9]
        flm -= (flm >= 9) ? 9 : 0;             // [0, 8]
        // ceil bin: flm+1 (slot 9 folds to 0 later), or flm itself if pint integral
        int   s2  = flm + ((pint != flf) ? 1 : 0);

        hist[flm][tid] += mag;
        hist[s2 ][tid] += mag;

        t0 = t1; t1 = t2;
        h0 = h1; h1 = h2;
    }
    __syncthreads();

    // ---- reduce per-thread hists -> 32 cells x 9 bins, write pooled output ----
    for (int i = tid; i < 32 * ORI; i += 256) {
        int cell = i / ORI;
        int b    = i - cell * ORI;
        int cy   = cell >> 2;          // 0..7
        int cx   = cell & 3;           // 0..3
        int tb   = cy * 32 + cx * 8;   // first tid of this cell

        float sum = 0.0f;
        #pragma unroll
        for (int j = 0; j < 8; j++) {
            sum += hist[b][tb + j];
            if (b == 0) sum += hist[9][tb + j];   // fold slot 9 -> bin 0
        }

        int ch = (row0 >> 3) + cy;
        int cw = (col0 >> 3) + cx;
        out[(size_t)n * (ORI * 64 * 64) + b * (64 * 64) + ch * 64 + cw] =
            sum * (1.0f / 64.0f);
    }
}

extern "C" void kernel_launch(void* const* d_in, const int* in_sizes, int n_in,
                              void* d_out, int out_size)
{
    const float* x   = (const float*)d_in[0];
    float*       out = (float*)d_out;

    dim3 grid(IMG_W / TILE_W, IMG_H / TILE_H, 64);
    hog_kernel<<<grid, 256>>>(x, out);
}

// round 4
// speedup vs baseline: 2.2153x; 1.4145x over previous
#include <cuda_runtime.h>

// HOG layer, fused: Sobel -> mag + comparison-based 9-bin orientation hist -> 8x8 mean pool.
// Input : x (64,1,512,512) fp32. Output: (64, 9*64*64) fp32.
//
// Bin math: bin = floor(9*atan2(gx,gy)/pi) mod 9 is invariant under theta -> theta+pi,
// so it depends only on cot(theta) = gy/gx. Monotone predicates p_k = [rat <= cot(k*pi/9)]
// give cumulative sums C_k = sum(mag * p_k); per-bin totals (floor + ceil contributions)
// are recovered via bin_b = C_{b-1} - C_{b+1} (bin0 = C0 - C1 + C8, bin8 = C7).
// No atan2, no atomics, no per-pixel histogram memory traffic.
//
// Block = 256 threads. Tile = 32 cols x 64 rows = 32 cells. Each thread column-walks
// 8 rows (exactly one cell) with register rotation: 3 LDS per pixel.

#define IMG_H 512
#define IMG_W 512
#define ORI   9

#define TILE_W 32
#define TILE_H 64
#define T_COLS 34   // 32 + 2 halo
#define T_ROWS 66   // 64 + 2 halo

__global__ __launch_bounds__(256) void hog_kernel(const float* __restrict__ x,
                                                  float* __restrict__ out)
{
    __shared__ float tile[T_ROWS][T_COLS];
    __shared__ float cellC[32][12];   // per-cell C0..C8; slots 9..10 zeroed

    const int n    = blockIdx.z;
    const int row0 = blockIdx.y * TILE_H;
    const int col0 = blockIdx.x * TILE_W;
    const int tid  = threadIdx.x;
    const int tx   = tid & 31;   // column within tile
    const int ty   = tid >> 5;   // cell-row group 0..7

    const float* __restrict__ img = x + (size_t)n * (IMG_H * IMG_W);

    // ---- cooperative halo-tile load (zero padding) ----
    for (int i = tid; i < T_ROWS * T_COLS; i += 256) {
        int r  = i / T_COLS;
        int c  = i - r * T_COLS;
        int gr = row0 + r - 1;
        int gc = col0 + c - 1;
        float v = 0.0f;
        if ((unsigned)gr < IMG_H && (unsigned)gc < IMG_W)
            v = img[gr * IMG_W + gc];
        tile[r][c] = v;
    }
    __syncthreads();

    // cot(k*pi/9), k = 1..8  (strictly decreasing)
    const float COT[8] = {
         2.7474774194546225f,
         1.1917535925942100f,
         0.5773502691896258f,
         0.1763269807084650f,
        -0.1763269807084650f,
        -0.5773502691896257f,
        -1.1917535925942100f,
        -2.7474774194546230f
    };

    float C[9];
    #pragma unroll
    for (int b = 0; b < 9; b++) C[b] = 0.0f;

    // ---- column walk: rows ty*8 .. ty*8+7 at column tx (one cell) ----
    const int rbase = ty * 8;

    float t0, t1, t2;   // left - right          per row
    float h0, h1, h2;   // left + 2*mid + right  per row
    {
        float l = tile[rbase][tx];
        float m = tile[rbase][tx + 1];
        float r = tile[rbase][tx + 2];
        t0 = l - r;  h0 = l + 2.0f * m + r;
        l = tile[rbase + 1][tx];
        m = tile[rbase + 1][tx + 1];
        r = tile[rbase + 1][tx + 2];
        t1 = l - r;  h1 = l + 2.0f * m + r;
    }

    #pragma unroll
    for (int s = 0; s < 8; s++) {
        float l = tile[rbase + s + 2][tx];
        float m = tile[rbase + s + 2][tx + 1];
        float r = tile[rbase + s + 2][tx + 2];
        t2 = l - r;  h2 = l + 2.0f * m + r;

        float gx = t0 + 2.0f * t1 + t2;
        float gy = h0 - h2;

        float r2  = fmaf(gx, gx, gy * gy);
        float mag = r2 * rsqrtf(r2);
        mag = (r2 == 0.0f) ? 0.0f : mag;     // guard 0 * inf = NaN

        float rat = __fdividef(gy, gx);      // cot(theta); +-inf when gx == 0

        C[0] += mag;
        #pragma unroll
        for (int k = 0; k < 8; k++)
            if (rat <= COT[k]) C[k + 1] += mag;

        t0 = t1; t1 = t2;
        h0 = h1; h1 = h2;
    }

    // ---- reduce C over the 8 threads of each cell (aligned 8-lane groups) ----
    #pragma unroll
    for (int b = 0; b < 9; b++) {
        #pragma unroll
        for (int d = 1; d < 8; d <<= 1)
            C[b] += __shfl_xor_sync(0xffffffffu, C[b], d);
    }

    if ((tid & 7) == 0) {
        int cell = tid >> 3;       // = ty*4 + cx
        #pragma unroll
        for (int b = 0; b < 9; b++) cellC[cell][b] = C[b];
        cellC[cell][9]  = 0.0f;
        cellC[cell][10] = 0.0f;
    }
    __syncthreads();

    // ---- recover bins and write pooled output: 32 cells x 9 bins = 288 values ----
    for (int i = tid; i < 32 * ORI; i += 256) {
        int cell = i / ORI;
        int b    = i - cell * ORI;

        float v;
        if (b == 0)
            v = cellC[cell][0] - cellC[cell][1] + cellC[cell][8];
        else
            v = cellC[cell][b - 1] - cellC[cell][b + 1];   // b=8 uses zeroed slot 9

        int cy = cell >> 2;            // 0..7
        int cx = cell & 3;             // 0..3
        int ch = (row0 >> 3) + cy;
        int cw = (col0 >> 3) + cx;
        out[(size_t)n * (ORI * 64 * 64) + b * (64 * 64) + ch * 64 + cw] =
            v * (1.0f / 64.0f);
    }
}

extern "C" void kernel_launch(void* const* d_in, const int* in_sizes, int n_in,
                              void* d_out, int out_size)
{
    const float* x   = (const float*)d_in[0];
    float*       out = (float*)d_out;

    dim3 grid(IMG_W / TILE_W, IMG_H / TILE_H, 64);
    hog_kernel<<<grid, 256>>>(x, out);
}

// round 5
// speedup vs baseline: 4.7131x; 2.1275x over previous
#include <cuda_runtime.h>

// HOG layer, fully register-resident: Sobel -> mag + comparison-based 9-bin
// orientation hist -> 8x8 mean pool. No shared memory, no atomics, no syncs.
// Input : x (64,1,512,512) fp32. Output: (64, 9*64*64) fp32.
//
// Thread = 4 cols x 8 rows patch (inside ONE 8x8 cell). Block = 128 threads
// = 16 col-groups (64 cols) x 8 row-groups (64 rows). Lane l and l^1 cover
// the two column-halves of the same cell -> cell reduce = one shfl.xor(1).
//
// Bin math (verified in R4): bin = floor(9*atan2(gx,gy)/pi) mod 9 depends only
// on cot(theta) = gy/gx; monotone predicates p_k = [rat <= cot(k*pi/9)] give
// cumulative sums C_k; bins recovered by bin_b = C_{b-1} - C_{b+1}
// (bin0 = C0 - C1 + C8, bin8 = C7).

#define ORI 9

__device__ __forceinline__ float fsqrt_approx(float v) {
    float y;
    asm("sqrt.approx.f32 %0, %1;" : "=f"(y) : "f"(v));
    return y;
}

struct RowTH { float t[4]; float h[4]; };

// Horizontal filter for 4 output columns of one image row.
// t_i = left - right, h_i = left + 2*mid + right.
__device__ __forceinline__ RowTH load_row(const float* __restrict__ img,
                                          int r, int c0,
                                          bool leftEdge, bool rightEdge)
{
    float4 v = make_float4(0.f, 0.f, 0.f, 0.f);
    float lf = 0.f, rt = 0.f;
    if ((unsigned)r < 512u) {
        const float* rp = img + r * 512;
        v = *reinterpret_cast<const float4*>(rp + c0);
        if (!leftEdge)  lf = __ldg(rp + c0 - 1);
        if (!rightEdge) rt = __ldg(rp + c0 + 4);
    }
    RowTH o;
    o.t[0] = lf  - v.y;  o.h[0] = fmaf(2.f, v.x, lf)  + v.y;
    o.t[1] = v.x - v.z;  o.h[1] = fmaf(2.f, v.y, v.x) + v.z;
    o.t[2] = v.y - v.w;  o.h[2] = fmaf(2.f, v.z, v.y) + v.w;
    o.t[3] = v.z - rt;   o.h[3] = fmaf(2.f, v.w, v.z) + rt;
    return o;
}

__global__ __launch_bounds__(128, 8) void hog_kernel(const float* __restrict__ x,
                                                     float* __restrict__ out)
{
    const int n    = blockIdx.z;
    const int row0 = blockIdx.y * 64;
    const int col0 = blockIdx.x * 64;
    const int tid  = threadIdx.x;
    const int cg   = tid & 15;        // col-group (4 cols each)
    const int rg   = tid >> 4;        // row-group (8 rows each)

    const int c0 = col0 + cg * 4;     // first output col of this thread
    const int r0 = row0 + rg * 8;     // first output row

    const float* __restrict__ img = x + (size_t)n * (512 * 512);

    const bool leftEdge  = (c0 == 0);
    const bool rightEdge = (c0 == 508);

    // cot(k*pi/9), k = 1..8 (strictly decreasing)
    const float COT[8] = {
         2.7474774194546225f,
         1.1917535925942100f,
         0.5773502691896258f,
         0.1763269807084650f,
        -0.1763269807084650f,
        -0.5773502691896257f,
        -1.1917535925942100f,
        -2.7474774194546230f
    };

    float C[9];
    #pragma unroll
    for (int b = 0; b < 9; b++) C[b] = 0.0f;

    RowTH a = load_row(img, r0 - 1, c0, leftEdge, rightEdge);
    RowTH b = load_row(img, r0,     c0, leftEdge, rightEdge);

    #pragma unroll
    for (int s = 0; s < 8; s++) {
        RowTH c = load_row(img, r0 + 1 + s, c0, leftEdge, rightEdge);

        #pragma unroll
        for (int i = 0; i < 4; i++) {
            float gx = fmaf(2.f, b.t[i], a.t[i]) + c.t[i];
            float gy = a.h[i] - c.h[i];

            float r2  = fmaf(gx, gx, gy * gy);
            float mag = fsqrt_approx(r2);          // sqrt.approx(0) == 0
            float rat = __fdividef(gy, gx);        // cot(theta)

            C[0] += mag;
            #pragma unroll
            for (int k = 0; k < 8; k++)
                if (rat <= COT[k]) C[k + 1] += mag;
        }
        a = b; b = c;
    }

    // ---- cell reduction: partner lane (lane^1) holds the other 4 columns ----
    #pragma unroll
    for (int q = 0; q < 9; q++)
        C[q] += __shfl_xor_sync(0xffffffffu, C[q], 1);

    // ---- recover bins, write pooled output (split 9 bins across the pair) ----
    const int ch = (row0 >> 3) + rg;
    const int cw = (col0 >> 3) + (cg >> 1);
    float* obase = out + (size_t)n * (ORI * 64 * 64) + ch * 64 + cw;

    float bins[9];
    bins[0] = C[0] - C[1] + C[8];
    #pragma unroll
    for (int q = 1; q < 8; q++) bins[q] = C[q - 1] - C[q + 1];
    bins[8] = C[7];

    if ((cg & 1) == 0) {
        #pragma unroll
        for (int q = 0; q < 5; q++)
            obase[q * 4096] = bins[q] * (1.0f / 64.0f);
    } else {
        #pragma unroll
        for (int q = 5; q < 9; q++)
            obase[q * 4096] = bins[q] * (1.0f / 64.0f);
    }
}

extern "C" void kernel_launch(void* const* d_in, const int* in_sizes, int n_in,
                              void* d_out, int out_size)
{
    const float* x   = (const float*)d_in[0];
    float*       out = (float*)d_out;

    dim3 grid(512 / 64, 512 / 64, 64);
    hog_kernel<<<grid, 128>>>(x, out);
}